// round 13
// baseline (speedup 1.0000x reference)
#include <cuda_runtime.h>
#include <cuda_bf16.h>

#define N_DIM 8
#define O_DIM 20
#define P_DIM 20
#define NTOT 32768
#define NPAIR (NTOT / 2)
#define THREADS 256           // 1 packed pair (2 samples)/thread -> 512 samples/CTA

typedef unsigned long long ull;
#define ONE2 0x3F8000003F800000ULL

// Column-scaled weight matrices (binom/cinv folded in by prep).
__device__ float g_Wm[P_DIM * 7 * O_DIM * O_DIM];      // [p][i][o][q]
__device__ float g_Wv[P_DIM * 6 * 7 * O_DIM * O_DIM];  // [p][k][i][o][q]
__device__ float g_w0m[P_DIM * O_DIM];
__device__ float g_w0v[P_DIM * 6 * O_DIM];
// Packed-pair Bernstein gate tables, COALESCED layout: [d][q][pair]
__device__ ull g_Bm[(size_t)N_DIM * O_DIM * NPAIR];    // plain
__device__ ull g_Bv[(size_t)N_DIM * O_DIM * NPAIR];    // squared
// Per-(perm,chain) partial sums: [P*7][N]
__device__ float g_scratch[P_DIM * 7 * NTOT];

__constant__ float c_binom[O_DIM] = {
    1.f, 19.f, 171.f, 969.f, 3876.f, 11628.f, 27132.f, 50388.f, 75582.f, 92378.f,
    92378.f, 75582.f, 50388.f, 27132.f, 11628.f, 3876.f, 969.f, 171.f, 19.f, 1.f};
__constant__ float c_cinv[6] = {1.0f, 1.f / 2, 1.f / 6, 1.f / 24, 1.f / 120, 1.f / 720};

// ---------------- packed f32x2 helpers ----------------
__device__ __forceinline__ ull fma2(ull a, ull b, ull c) {
    ull d; asm("fma.rn.f32x2 %0, %1, %2, %3;" : "=l"(d) : "l"(a), "l"(b), "l"(c)); return d;
}
__device__ __forceinline__ ull mul2(ull a, ull b) {
    ull d; asm("mul.rn.f32x2 %0, %1, %2;" : "=l"(d) : "l"(a), "l"(b)); return d;
}
__device__ __forceinline__ ull add2(ull a, ull b) {
    ull d; asm("add.rn.f32x2 %0, %1, %2;" : "=l"(d) : "l"(a), "l"(b)); return d;
}
__device__ __forceinline__ ull pack2(float lo, float hi) {
    ull d; asm("mov.b64 %0, {%1, %2};" : "=l"(d) : "f"(lo), "f"(hi)); return d;
}
__device__ __forceinline__ void unpack2(ull v, float& lo, float& hi) {
    asm("mov.b64 {%0, %1}, %2;" : "=f"(lo), "=f"(hi) : "l"(v));
}

// ---------------------------------------------------------------------------
// Prep A: W' = exp(...) column-scaled by binom[q]^(1 or 2); cinv folded in w0v.
// ---------------------------------------------------------------------------
__global__ void prep_kernel(const float* __restrict__ meanw0,
                            const float* __restrict__ meanw,
                            const float* __restrict__ varw0,
                            const float* __restrict__ varw) {
    int idx = blockIdx.x * blockDim.x + threadIdx.x;
    if (idx < 56000) {
        int oq = idx % 400;  int q = oq % 20;
        int r = idx / 400;   int i = r % 7;  int p = r / 7;
        g_Wm[idx] = expf(meanw[(i * 20 + p) * 400 + oq]) * c_binom[q];
    } else if (idx < 392000) {
        int j = idx - 56000;
        int oq = j % 400;  int q = oq % 20;
        int r = j / 400;   int i = r % 7;  int k = (r / 7) % 6;  int p = r / 42;
        float m = meanw[(i * 20 + p) * 400 + oq];
        float v = varw[(i * 20 + p) * 400 + oq];
        g_Wv[j] = expf(2.0f * m + (float)(k + 1) * v) * c_binom[q] * c_binom[q];
    } else if (idx < 392400) {
        int j = idx - 392000;  int q = j % 20;
        g_w0m[j] = expf(meanw0[j]) * c_binom[q];
    } else if (idx < 394800) {
        int j = idx - 392400;
        int q = j % 20;  int k = (j / 20) % 6;  int p = j / 120;
        g_w0v[j] = expf(2.0f * meanw0[p * 20 + q] + (float)(k + 1) * varw0[p * 20 + q]) *
                   c_binom[q] * c_binom[q] * c_cinv[k];
    }
}

// ---------------------------------------------------------------------------
// Prep B: gate tables t[q] = x^q (1-x)^(19-q) (and squared), [d][q][pair].
// ---------------------------------------------------------------------------
__global__ void prep_basis_kernel(const float* __restrict__ X) {
    int i = blockIdx.x * blockDim.x + threadIdx.x;
    if (i >= NPAIR) return;
    const float4* XA = (const float4*)(X + (size_t)(2 * i) * N_DIM);
    float4 a0 = XA[0], a1 = XA[1], b0 = XA[2], b1 = XA[3];
    float xa[8] = {a0.x, a0.y, a0.z, a0.w, a1.x, a1.y, a1.z, a1.w};
    float xb[8] = {b0.x, b0.y, b0.z, b0.w, b1.x, b1.y, b1.z, b1.w};
#pragma unroll
    for (int d = 0; d < N_DIM; ++d) {
        ull x = pack2(xa[d], xb[d]);
        ull omx = pack2(1.0f - xa[d], 1.0f - xb[d]);
        ull t[O_DIM];
        t[0] = ONE2;
#pragma unroll
        for (int q = 1; q < O_DIM; ++q) t[q] = mul2(t[q - 1], x);
        ull qk = ONE2;
#pragma unroll
        for (int q = O_DIM - 2; q >= 0; --q) {
            qk = mul2(qk, omx);
            t[q] = mul2(t[q], qk);
        }
#pragma unroll
        for (int q = 0; q < O_DIM; ++q) {
            g_Bm[((size_t)d * O_DIM + q) * NPAIR + i] = t[q];
            g_Bv[((size_t)d * O_DIM + q) * NPAIR + i] = mul2(t[q], t[q]);
        }
    }
}

// Dynamic smem (bytes): sW2 22400 + sW02 160 + sPerm 32
#define SMEM_BYTES (22400 + 160 + 32)

// One CTA = one (perm p, chain c) over a 512-sample tile. 1 pair per thread.
// Consume-side gating: u_{i+1}[q] = sum_o (u_i[o] * t_i[o]) * W[o][q].
__global__ __launch_bounds__(THREADS, 2) void main_kernel(const int* __restrict__ perm,
                                                          int ntiles) {
    extern __shared__ char smem[];
    ulonglong2* sW2 = (ulonglong2*)smem;                   // 22400 B
    ull* sW02 = (ull*)(smem + 22400);                      // 20 ull
    int* sPerm = (int*)(sW02 + O_DIM);

    const int t = threadIdx.x;
    const int tile = blockIdx.x % ntiles;
    const int pc = blockIdx.x / ntiles;                    // p*7 + c
    const int p = pc / 7;
    const int c = pc % 7;
    const int i1 = tile * THREADS + t;                     // this thread's pair

    if (t < N_DIM) sPerm[t] = perm[p * N_DIM + t];

    // ---- stage W from compact float table, duplicate at smem store ----
    {
        const float* wsrc = (c == 0) ? (g_Wm + p * 2800)
                                     : (g_Wv + (p * 6 + (c - 1)) * 2800);
        const float* w0src = (c == 0) ? (g_w0m + p * O_DIM)
                                      : (g_w0v + (p * 6 + (c - 1)) * O_DIM);
        const float4* src4 = (const float4*)wsrc;
        float4* dst4 = (float4*)sW2;
#pragma unroll 1
        for (int j = t; j < 700; j += THREADS) {
            float4 v = src4[j];
            dst4[2 * j]     = make_float4(v.x, v.x, v.y, v.y);
            dst4[2 * j + 1] = make_float4(v.z, v.z, v.w, v.w);
        }
        if (t < O_DIM) {
            float w = w0src[t];
            sW02[t] = pack2(w, w);
        }
    }
    __syncthreads();

    const ull* __restrict__ Bt = (c == 0) ? g_Bm : g_Bv;

    // u init = w0 (ungated; gate of dim sPerm[0] applied at first consumption)
    ull u[O_DIM];
#pragma unroll
    for (int q = 0; q < O_DIM; ++q) u[q] = sW02[q];

#pragma unroll 1
    for (int i = 0; i < 7; ++i) {
        const int di = sPerm[i];
        const ull* gp = Bt + (size_t)di * O_DIM * NPAIR + i1;
        ull tlo[10];
#pragma unroll
        for (int q = 0; q < 10; ++q) tlo[q] = gp[(size_t)q * NPAIR];
        ull thi[10];
        ull g[O_DIM];
        const ulonglong2* wb = sW2 + i * 200;
#pragma unroll
        for (int o = 0; o < O_DIM; ++o) {
            if (o == 5) {
#pragma unroll
                for (int q = 0; q < 10; ++q)
                    thi[q] = gp[(size_t)(10 + q) * NPAIR];
            }
            ull a = mul2(u[o], (o < 10) ? tlo[o] : thi[o - 10]);
            const ulonglong2* wr = wb + o * 10;
#pragma unroll
            for (int j = 0; j < 10; ++j) {
                ulonglong2 w = wr[j];   // (w2q,w2q | w2q+1,w2q+1)
                if (o == 0) {
                    g[2 * j]     = mul2(a, w.x);
                    g[2 * j + 1] = mul2(a, w.y);
                } else {
                    g[2 * j]     = fma2(a, w.x, g[2 * j]);
                    g[2 * j + 1] = fma2(a, w.y, g[2 * j + 1]);
                }
            }
        }
#pragma unroll
        for (int q = 0; q < O_DIM; ++q) u[q] = g[q];
    }

    // ---- final gated dot with dim sPerm[7] ----
    float s0, s1;
    {
        const int d7 = sPerm[7];
        const ull* gp = Bt + (size_t)d7 * O_DIM * NPAIR + i1;
        ull se = 0ULL, so = 0ULL;
#pragma unroll
        for (int q = 0; q < O_DIM; ++q) {
            ull tg = gp[(size_t)q * NPAIR];
            if (q & 1) so = fma2(u[q], tg, so);
            else       se = fma2(u[q], tg, se);
        }
        unpack2(add2(se, so), s0, s1);
    }
    *(float2*)(g_scratch + (size_t)pc * NTOT + i1 * 2) = make_float2(s0, s1);
}

// 4 threads per output; each sums 35 pc slots (5 mean + 30 var; j%7==0 -> mean).
__global__ void reduce_kernel(float* __restrict__ out, int n) {
    int tid = threadIdx.x;
    int i = blockIdx.x * 64 + (tid >> 2);    // output sample
    int sub = tid & 3;
    if (i >= n) return;
    float m = 0.0f, v = 0.0f;
    int base = sub * 35;
#pragma unroll
    for (int j = 0; j < 35; ++j) {
        float s = g_scratch[(size_t)(base + j) * NTOT + i];
        if (j % 7 == 0) m += s; else v += s;
    }
    m += __shfl_xor_sync(0xFFFFFFFFu, m, 1);
    v += __shfl_xor_sync(0xFFFFFFFFu, v, 1);
    m += __shfl_xor_sync(0xFFFFFFFFu, m, 2);
    v += __shfl_xor_sync(0xFFFFFFFFu, v, 2);
    if (sub == 0) ((float2*)out)[i] = make_float2(m, v);
}

extern "C" void kernel_launch(void* const* d_in, const int* in_sizes, int n_in,
                              void* d_out, int out_size) {
    const float* X = (const float*)d_in[0];       // [N, 8]
    const int* perm = (const int*)d_in[1];        // [20, 8]
    const float* meanw0 = (const float*)d_in[2];  // [20, 1, 20]
    const float* meanw = (const float*)d_in[3];   // [7, 20, 20, 20]
    const float* varw0 = (const float*)d_in[4];   // [20, 1, 20]
    const float* varw = (const float*)d_in[5];    // [7, 20, 20, 20]
    float* out = (float*)d_out;                   // [N, 2]

    int N = in_sizes[0] / N_DIM;
    int ntiles = N / (2 * THREADS);               // 64 for N=32768

    prep_kernel<<<(394800 + 255) / 256, 256>>>(meanw0, meanw, varw0, varw);
    prep_basis_kernel<<<(NPAIR + 255) / 256, 256>>>(X);

    cudaFuncSetAttribute(main_kernel, cudaFuncAttributeMaxDynamicSharedMemorySize,
                         SMEM_BYTES);
    main_kernel<<<P_DIM * 7 * ntiles, THREADS, SMEM_BYTES>>>(perm, ntiles);

    reduce_kernel<<<(N + 63) / 64, 256>>>(out, N);
}

// round 14
// speedup vs baseline: 2.4518x; 2.4518x over previous
#include <cuda_runtime.h>
#include <cuda_bf16.h>

#define N_DIM 8
#define O_DIM 20
#define P_DIM 20
#define NTOT 32768
#define NPAIR (NTOT / 2)
#define QSTRIDE (NPAIR / 2)   // ulonglong2 stride between q slots
#define THREADS 128           // 4 samples/thread -> 512 samples/CTA

typedef unsigned long long ull;
#define ONE2 0x3F8000003F800000ULL

// Column-scaled weight matrices (binom/cinv folded in by prep).
__device__ float g_Wm[P_DIM * 7 * O_DIM * O_DIM];      // [p][i][o][q]
__device__ float g_Wv[P_DIM * 6 * 7 * O_DIM * O_DIM];  // [p][k][i][o][q]
__device__ float g_w0m[P_DIM * O_DIM];
__device__ float g_w0v[P_DIM * 6 * O_DIM];
// Packed-pair Bernstein gate tables, COALESCED layout: [d][q][pair]
__device__ ull g_Bm[(size_t)N_DIM * O_DIM * NPAIR];    // plain
__device__ ull g_Bv[(size_t)N_DIM * O_DIM * NPAIR];    // squared
// Per-(perm,chain) partial sums: [P*7][N]
__device__ float g_scratch[P_DIM * 7 * NTOT];

__constant__ float c_binom[O_DIM] = {
    1.f, 19.f, 171.f, 969.f, 3876.f, 11628.f, 27132.f, 50388.f, 75582.f, 92378.f,
    92378.f, 75582.f, 50388.f, 27132.f, 11628.f, 3876.f, 969.f, 171.f, 19.f, 1.f};
__constant__ float c_cinv[6] = {1.0f, 1.f / 2, 1.f / 6, 1.f / 24, 1.f / 120, 1.f / 720};

// ---------------- packed f32x2 helpers ----------------
__device__ __forceinline__ ull fma2(ull a, ull b, ull c) {
    ull d; asm("fma.rn.f32x2 %0, %1, %2, %3;" : "=l"(d) : "l"(a), "l"(b), "l"(c)); return d;
}
__device__ __forceinline__ ull mul2(ull a, ull b) {
    ull d; asm("mul.rn.f32x2 %0, %1, %2;" : "=l"(d) : "l"(a), "l"(b)); return d;
}
__device__ __forceinline__ ull add2(ull a, ull b) {
    ull d; asm("add.rn.f32x2 %0, %1, %2;" : "=l"(d) : "l"(a), "l"(b)); return d;
}
__device__ __forceinline__ ull pack2(float lo, float hi) {
    ull d; asm("mov.b64 %0, {%1, %2};" : "=l"(d) : "f"(lo), "f"(hi)); return d;
}
__device__ __forceinline__ void unpack2(ull v, float& lo, float& hi) {
    asm("mov.b64 {%0, %1}, %2;" : "=f"(lo), "=f"(hi) : "l"(v));
}
__device__ __forceinline__ void prefetchL1(const void* p) {
    asm volatile("prefetch.global.L1 [%0];" :: "l"(p));
}

// ---------------------------------------------------------------------------
// Prep A: W' = exp(...) column-scaled by binom[q]^(1 or 2); cinv folded in w0v.
// ---------------------------------------------------------------------------
__global__ void prep_kernel(const float* __restrict__ meanw0,
                            const float* __restrict__ meanw,
                            const float* __restrict__ varw0,
                            const float* __restrict__ varw) {
    int idx = blockIdx.x * blockDim.x + threadIdx.x;
    if (idx < 56000) {
        int oq = idx % 400;  int q = oq % 20;
        int r = idx / 400;   int i = r % 7;  int p = r / 7;
        g_Wm[idx] = expf(meanw[(i * 20 + p) * 400 + oq]) * c_binom[q];
    } else if (idx < 392000) {
        int j = idx - 56000;
        int oq = j % 400;  int q = oq % 20;
        int r = j / 400;   int i = r % 7;  int k = (r / 7) % 6;  int p = r / 42;
        float m = meanw[(i * 20 + p) * 400 + oq];
        float v = varw[(i * 20 + p) * 400 + oq];
        g_Wv[j] = expf(2.0f * m + (float)(k + 1) * v) * c_binom[q] * c_binom[q];
    } else if (idx < 392400) {
        int j = idx - 392000;  int q = j % 20;
        g_w0m[j] = expf(meanw0[j]) * c_binom[q];
    } else if (idx < 394800) {
        int j = idx - 392400;
        int q = j % 20;  int k = (j / 20) % 6;  int p = j / 120;
        g_w0v[j] = expf(2.0f * meanw0[p * 20 + q] + (float)(k + 1) * varw0[p * 20 + q]) *
                   c_binom[q] * c_binom[q] * c_cinv[k];
    }
}

// ---------------------------------------------------------------------------
// Prep B: gate tables t[q] = x^q (1-x)^(19-q) (and squared), [d][q][pair].
// ---------------------------------------------------------------------------
__global__ void prep_basis_kernel(const float* __restrict__ X) {
    int i = blockIdx.x * blockDim.x + threadIdx.x;
    if (i >= NPAIR) return;
    const float4* XA = (const float4*)(X + (size_t)(2 * i) * N_DIM);
    float4 a0 = XA[0], a1 = XA[1], b0 = XA[2], b1 = XA[3];
    float xa[8] = {a0.x, a0.y, a0.z, a0.w, a1.x, a1.y, a1.z, a1.w};
    float xb[8] = {b0.x, b0.y, b0.z, b0.w, b1.x, b1.y, b1.z, b1.w};
#pragma unroll
    for (int d = 0; d < N_DIM; ++d) {
        ull x = pack2(xa[d], xb[d]);
        ull omx = pack2(1.0f - xa[d], 1.0f - xb[d]);
        ull t[O_DIM];
        t[0] = ONE2;
#pragma unroll
        for (int q = 1; q < O_DIM; ++q) t[q] = mul2(t[q - 1], x);
        ull qk = ONE2;
#pragma unroll
        for (int q = O_DIM - 2; q >= 0; --q) {
            qk = mul2(qk, omx);
            t[q] = mul2(t[q], qk);
        }
#pragma unroll
        for (int q = 0; q < O_DIM; ++q) {
            g_Bm[((size_t)d * O_DIM + q) * NPAIR + i] = t[q];
            g_Bv[((size_t)d * O_DIM + q) * NPAIR + i] = mul2(t[q], t[q]);
        }
    }
}

// Dynamic smem (bytes): sW2 22400 + sW02 160 + sPerm 32
#define SMEM_BYTES (22400 + 160 + 32)

// One CTA = one (perm p, chain c) over a 512-sample tile. 2 packed pairs/thread.
// Consume-side gating: u_{i+1}[q] = sum_o (u_i[o] * t_i[o]) * W[o][q].
// Next-step gate lines prefetched to L1 mid-matmul (zero register cost).
__global__ __launch_bounds__(THREADS, 2) void main_kernel(const int* __restrict__ perm,
                                                          int ntiles) {
    extern __shared__ char smem[];
    ulonglong2* sW2 = (ulonglong2*)smem;                   // 22400 B
    ull* sW02 = (ull*)(smem + 22400);                      // 20 ull
    int* sPerm = (int*)(sW02 + O_DIM);

    const int t = threadIdx.x;
    const int tile = blockIdx.x % ntiles;
    const int pc = blockIdx.x / ntiles;                    // p*7 + c
    const int p = pc / 7;
    const int c = pc % 7;
    const int i1 = (tile * THREADS + t) * 2;               // even pair index

    if (t < N_DIM) sPerm[t] = perm[p * N_DIM + t];

    // ---- stage W from compact float table, duplicate at smem store ----
    {
        const float* wsrc = (c == 0) ? (g_Wm + p * 2800)
                                     : (g_Wv + (p * 6 + (c - 1)) * 2800);
        const float* w0src = (c == 0) ? (g_w0m + p * O_DIM)
                                      : (g_w0v + (p * 6 + (c - 1)) * O_DIM);
        const float4* src4 = (const float4*)wsrc;
        float4* dst4 = (float4*)sW2;
#pragma unroll 1
        for (int j = t; j < 700; j += THREADS) {
            float4 v = src4[j];
            dst4[2 * j]     = make_float4(v.x, v.x, v.y, v.y);
            dst4[2 * j + 1] = make_float4(v.z, v.z, v.w, v.w);
        }
        if (t < O_DIM) {
            float w = w0src[t];
            sW02[t] = pack2(w, w);
        }
    }
    __syncthreads();

    const ull* __restrict__ Bt = (c == 0) ? g_Bm : g_Bv;

    // u init = w0 (ungated; gate of dim sPerm[0] applied at first consumption)
    ull u1[O_DIM], u2[O_DIM];
#pragma unroll
    for (int q = 0; q < O_DIM; ++q) { u1[q] = sW02[q]; u2[q] = sW02[q]; }

#pragma unroll 1
    for (int i = 0; i < 7; ++i) {
        const int di = sPerm[i];
        const ulonglong2* gp =
            (const ulonglong2*)(Bt + (size_t)di * O_DIM * NPAIR + i1);
        // next step's gate base (i+1 <= 7 always valid; i==6 -> final-dot gates)
        const ulonglong2* gpn =
            (const ulonglong2*)(Bt + (size_t)sPerm[i + 1] * O_DIM * NPAIR + i1);
        ulonglong2 tlo[10];
#pragma unroll
        for (int q = 0; q < 10; ++q) tlo[q] = gp[(size_t)q * QSTRIDE];
        ulonglong2 thi[10];
        ull g1[O_DIM], g2[O_DIM];
        const ulonglong2* wb = sW2 + i * 200;
#pragma unroll
        for (int o = 0; o < O_DIM; ++o) {
            if (o == 5) {
#pragma unroll
                for (int q = 0; q < 10; ++q)
                    thi[q] = gp[(size_t)(10 + q) * QSTRIDE];
            }
            if (o == 10) {
#pragma unroll
                for (int q = 0; q < 10; ++q)
                    prefetchL1(gpn + (size_t)q * QSTRIDE);
            }
            if (o == 15) {
#pragma unroll
                for (int q = 10; q < 20; ++q)
                    prefetchL1(gpn + (size_t)q * QSTRIDE);
            }
            ulonglong2 tg = (o < 10) ? tlo[o] : thi[o - 10];
            ull a1 = mul2(u1[o], tg.x);
            ull a2 = mul2(u2[o], tg.y);
            const ulonglong2* wr = wb + o * 10;
#pragma unroll
            for (int j = 0; j < 10; ++j) {
                ulonglong2 w = wr[j];   // (w2q,w2q | w2q+1,w2q+1)
                if (o == 0) {
                    g1[2 * j]     = mul2(a1, w.x);
                    g2[2 * j]     = mul2(a2, w.x);
                    g1[2 * j + 1] = mul2(a1, w.y);
                    g2[2 * j + 1] = mul2(a2, w.y);
                } else {
                    g1[2 * j]     = fma2(a1, w.x, g1[2 * j]);
                    g2[2 * j]     = fma2(a2, w.x, g2[2 * j]);
                    g1[2 * j + 1] = fma2(a1, w.y, g1[2 * j + 1]);
                    g2[2 * j + 1] = fma2(a2, w.y, g2[2 * j + 1]);
                }
            }
        }
#pragma unroll
        for (int q = 0; q < O_DIM; ++q) { u1[q] = g1[q]; u2[q] = g2[q]; }
    }

    // ---- final gated dot with dim sPerm[7] (lines already prefetched) ----
    float s0, s1, s2, s3;
    {
        const int d7 = sPerm[7];
        const ulonglong2* gp =
            (const ulonglong2*)(Bt + (size_t)d7 * O_DIM * NPAIR + i1);
        ull se1 = 0ULL, so1 = 0ULL, se2 = 0ULL, so2 = 0ULL;
#pragma unroll
        for (int q = 0; q < O_DIM; ++q) {
            ulonglong2 tg = gp[(size_t)q * QSTRIDE];
            if (q & 1) {
                so1 = fma2(u1[q], tg.x, so1);
                so2 = fma2(u2[q], tg.y, so2);
            } else {
                se1 = fma2(u1[q], tg.x, se1);
                se2 = fma2(u2[q], tg.y, se2);
            }
        }
        unpack2(add2(se1, so1), s0, s1);
        unpack2(add2(se2, so2), s2, s3);
    }
    *(float4*)(g_scratch + (size_t)pc * NTOT + i1 * 2) = make_float4(s0, s1, s2, s3);
}

// 4 threads per output; each sums 35 pc slots (5 mean + 30 var; j%7==0 -> mean).
__global__ void reduce_kernel(float* __restrict__ out, int n) {
    int tid = threadIdx.x;
    int i = blockIdx.x * 64 + (tid >> 2);    // output sample
    int sub = tid & 3;
    if (i >= n) return;
    float m = 0.0f, v = 0.0f;
    int base = sub * 35;
#pragma unroll
    for (int j = 0; j < 35; ++j) {
        float s = g_scratch[(size_t)(base + j) * NTOT + i];
        if (j % 7 == 0) m += s; else v += s;
    }
    m += __shfl_xor_sync(0xFFFFFFFFu, m, 1);
    v += __shfl_xor_sync(0xFFFFFFFFu, v, 1);
    m += __shfl_xor_sync(0xFFFFFFFFu, m, 2);
    v += __shfl_xor_sync(0xFFFFFFFFu, v, 2);
    if (sub == 0) ((float2*)out)[i] = make_float2(m, v);
}

extern "C" void kernel_launch(void* const* d_in, const int* in_sizes, int n_in,
                              void* d_out, int out_size) {
    const float* X = (const float*)d_in[0];       // [N, 8]
    const int* perm = (const int*)d_in[1];        // [20, 8]
    const float* meanw0 = (const float*)d_in[2];  // [20, 1, 20]
    const float* meanw = (const float*)d_in[3];   // [7, 20, 20, 20]
    const float* varw0 = (const float*)d_in[4];   // [20, 1, 20]
    const float* varw = (const float*)d_in[5];    // [7, 20, 20, 20]
    float* out = (float*)d_out;                   // [N, 2]

    int N = in_sizes[0] / N_DIM;
    int ntiles = N / (4 * THREADS);               // 64 for N=32768

    prep_kernel<<<(394800 + 255) / 256, 256>>>(meanw0, meanw, varw0, varw);
    prep_basis_kernel<<<(NPAIR + 255) / 256, 256>>>(X);

    cudaFuncSetAttribute(main_kernel, cudaFuncAttributeMaxDynamicSharedMemorySize,
                         SMEM_BYTES);
    main_kernel<<<P_DIM * 7 * ntiles, THREADS, SMEM_BYTES>>>(perm, ntiles);

    reduce_kernel<<<(N + 63) / 64, 256>>>(out, N);
}

// round 15
// speedup vs baseline: 2.4996x; 1.0195x over previous
#include <cuda_runtime.h>
#include <cuda_bf16.h>

#define N_DIM 8
#define O_DIM 20
#define P_DIM 20
#define NTOT 32768
#define NPAIR (NTOT / 2)
#define QSTRIDE (NPAIR / 2)   // ulonglong2 stride between q slots
#define THREADS 128           // 4 samples/thread -> 512 samples/CTA
#define GWIN 6                // rolling gate window depth

typedef unsigned long long ull;
#define ONE2 0x3F8000003F800000ULL

// Column-scaled weight matrices (binom/cinv folded in by prep).
__device__ float g_Wm[P_DIM * 7 * O_DIM * O_DIM];      // [p][i][o][q]
__device__ float g_Wv[P_DIM * 6 * 7 * O_DIM * O_DIM];  // [p][k][i][o][q]
__device__ float g_w0m[P_DIM * O_DIM];
__device__ float g_w0v[P_DIM * 6 * O_DIM];
// Packed-pair Bernstein gate tables, COALESCED layout: [d][q][pair]
__device__ ull g_Bm[(size_t)N_DIM * O_DIM * NPAIR];    // plain
__device__ ull g_Bv[(size_t)N_DIM * O_DIM * NPAIR];    // squared
// Per-(perm,chain) partial sums: [P*7][N]
__device__ float g_scratch[P_DIM * 7 * NTOT];

__constant__ float c_binom[O_DIM] = {
    1.f, 19.f, 171.f, 969.f, 3876.f, 11628.f, 27132.f, 50388.f, 75582.f, 92378.f,
    92378.f, 75582.f, 50388.f, 27132.f, 11628.f, 3876.f, 969.f, 171.f, 19.f, 1.f};
__constant__ float c_cinv[6] = {1.0f, 1.f / 2, 1.f / 6, 1.f / 24, 1.f / 120, 1.f / 720};

// ---------------- packed f32x2 helpers ----------------
__device__ __forceinline__ ull fma2(ull a, ull b, ull c) {
    ull d; asm("fma.rn.f32x2 %0, %1, %2, %3;" : "=l"(d) : "l"(a), "l"(b), "l"(c)); return d;
}
__device__ __forceinline__ ull mul2(ull a, ull b) {
    ull d; asm("mul.rn.f32x2 %0, %1, %2;" : "=l"(d) : "l"(a), "l"(b)); return d;
}
__device__ __forceinline__ ull add2(ull a, ull b) {
    ull d; asm("add.rn.f32x2 %0, %1, %2;" : "=l"(d) : "l"(a), "l"(b)); return d;
}
__device__ __forceinline__ ull pack2(float lo, float hi) {
    ull d; asm("mov.b64 %0, {%1, %2};" : "=l"(d) : "f"(lo), "f"(hi)); return d;
}
__device__ __forceinline__ void unpack2(ull v, float& lo, float& hi) {
    asm("mov.b64 {%0, %1}, %2;" : "=f"(lo), "=f"(hi) : "l"(v));
}

// ---------------------------------------------------------------------------
// Prep A: W' = exp(...) column-scaled by binom[q]^(1 or 2); cinv folded in w0v.
// ---------------------------------------------------------------------------
__global__ void prep_kernel(const float* __restrict__ meanw0,
                            const float* __restrict__ meanw,
                            const float* __restrict__ varw0,
                            const float* __restrict__ varw) {
    int idx = blockIdx.x * blockDim.x + threadIdx.x;
    if (idx < 56000) {
        int oq = idx % 400;  int q = oq % 20;
        int r = idx / 400;   int i = r % 7;  int p = r / 7;
        g_Wm[idx] = expf(meanw[(i * 20 + p) * 400 + oq]) * c_binom[q];
    } else if (idx < 392000) {
        int j = idx - 56000;
        int oq = j % 400;  int q = oq % 20;
        int r = j / 400;   int i = r % 7;  int k = (r / 7) % 6;  int p = r / 42;
        float m = meanw[(i * 20 + p) * 400 + oq];
        float v = varw[(i * 20 + p) * 400 + oq];
        g_Wv[j] = expf(2.0f * m + (float)(k + 1) * v) * c_binom[q] * c_binom[q];
    } else if (idx < 392400) {
        int j = idx - 392000;  int q = j % 20;
        g_w0m[j] = expf(meanw0[j]) * c_binom[q];
    } else if (idx < 394800) {
        int j = idx - 392400;
        int q = j % 20;  int k = (j / 20) % 6;  int p = j / 120;
        g_w0v[j] = expf(2.0f * meanw0[p * 20 + q] + (float)(k + 1) * varw0[p * 20 + q]) *
                   c_binom[q] * c_binom[q] * c_cinv[k];
    }
}

// ---------------------------------------------------------------------------
// Prep B: gate tables t[q] = x^q (1-x)^(19-q) (and squared), [d][q][pair].
// ---------------------------------------------------------------------------
__global__ void prep_basis_kernel(const float* __restrict__ X) {
    int i = blockIdx.x * blockDim.x + threadIdx.x;
    if (i >= NPAIR) return;
    const float4* XA = (const float4*)(X + (size_t)(2 * i) * N_DIM);
    float4 a0 = XA[0], a1 = XA[1], b0 = XA[2], b1 = XA[3];
    float xa[8] = {a0.x, a0.y, a0.z, a0.w, a1.x, a1.y, a1.z, a1.w};
    float xb[8] = {b0.x, b0.y, b0.z, b0.w, b1.x, b1.y, b1.z, b1.w};
#pragma unroll
    for (int d = 0; d < N_DIM; ++d) {
        ull x = pack2(xa[d], xb[d]);
        ull omx = pack2(1.0f - xa[d], 1.0f - xb[d]);
        ull t[O_DIM];
        t[0] = ONE2;
#pragma unroll
        for (int q = 1; q < O_DIM; ++q) t[q] = mul2(t[q - 1], x);
        ull qk = ONE2;
#pragma unroll
        for (int q = O_DIM - 2; q >= 0; --q) {
            qk = mul2(qk, omx);
            t[q] = mul2(t[q], qk);
        }
#pragma unroll
        for (int q = 0; q < O_DIM; ++q) {
            g_Bm[((size_t)d * O_DIM + q) * NPAIR + i] = t[q];
            g_Bv[((size_t)d * O_DIM + q) * NPAIR + i] = mul2(t[q], t[q]);
        }
    }
}

// Dynamic smem (bytes): sW2 22400 + sW02 160 + sPerm 32
#define SMEM_BYTES (22400 + 160 + 32)

// One CTA = one (perm p, chain c) over a 512-sample tile. 2 packed pairs/thread.
// Consume-side gating: u_{i+1}[q] = sum_o (u_i[o] * t_i[o]) * W[o][q].
// Gates streamed through a rolling GWIN-deep register window (load o+GWIN
// while consuming o) — short live ranges, ~5 o-iterations of load-ahead.
__global__ __launch_bounds__(THREADS, 2) void main_kernel(const int* __restrict__ perm,
                                                          int ntiles) {
    extern __shared__ char smem[];
    ulonglong2* sW2 = (ulonglong2*)smem;                   // 22400 B
    ull* sW02 = (ull*)(smem + 22400);                      // 20 ull
    int* sPerm = (int*)(sW02 + O_DIM);

    const int t = threadIdx.x;
    const int tile = blockIdx.x % ntiles;
    const int pc = blockIdx.x / ntiles;                    // p*7 + c
    const int p = pc / 7;
    const int c = pc % 7;
    const int i1 = (tile * THREADS + t) * 2;               // even pair index

    if (t < N_DIM) sPerm[t] = perm[p * N_DIM + t];

    // ---- stage W from compact float table, duplicate at smem store ----
    {
        const float* wsrc = (c == 0) ? (g_Wm + p * 2800)
                                     : (g_Wv + (p * 6 + (c - 1)) * 2800);
        const float* w0src = (c == 0) ? (g_w0m + p * O_DIM)
                                      : (g_w0v + (p * 6 + (c - 1)) * O_DIM);
        const float4* src4 = (const float4*)wsrc;
        float4* dst4 = (float4*)sW2;
#pragma unroll 1
        for (int j = t; j < 700; j += THREADS) {
            float4 v = src4[j];
            dst4[2 * j]     = make_float4(v.x, v.x, v.y, v.y);
            dst4[2 * j + 1] = make_float4(v.z, v.z, v.w, v.w);
        }
        if (t < O_DIM) {
            float w = w0src[t];
            sW02[t] = pack2(w, w);
        }
    }
    __syncthreads();

    const ull* __restrict__ Bt = (c == 0) ? g_Bm : g_Bv;

    // u init = w0 (ungated; gate of dim sPerm[0] applied at first consumption)
    ull u1[O_DIM], u2[O_DIM];
#pragma unroll
    for (int q = 0; q < O_DIM; ++q) { u1[q] = sW02[q]; u2[q] = sW02[q]; }

#pragma unroll 1
    for (int i = 0; i < 7; ++i) {
        const int di = sPerm[i];
        const ulonglong2* gp =
            (const ulonglong2*)(Bt + (size_t)di * O_DIM * NPAIR + i1);
        // rolling gate window
        ulonglong2 tg[GWIN];
#pragma unroll
        for (int q = 0; q < GWIN; ++q) tg[q] = gp[(size_t)q * QSTRIDE];
        ull g1[O_DIM], g2[O_DIM];
        const ulonglong2* wb = sW2 + i * 200;
#pragma unroll
        for (int o = 0; o < O_DIM; ++o) {
            ulonglong2 cur = tg[o % GWIN];
            if (o + GWIN < O_DIM)
                tg[o % GWIN] = gp[(size_t)(o + GWIN) * QSTRIDE];
            ull a1 = mul2(u1[o], cur.x);
            ull a2 = mul2(u2[o], cur.y);
            const ulonglong2* wr = wb + o * 10;
#pragma unroll
            for (int j = 0; j < 10; ++j) {
                ulonglong2 w = wr[j];   // (w2q,w2q | w2q+1,w2q+1)
                if (o == 0) {
                    g1[2 * j]     = mul2(a1, w.x);
                    g2[2 * j]     = mul2(a2, w.x);
                    g1[2 * j + 1] = mul2(a1, w.y);
                    g2[2 * j + 1] = mul2(a2, w.y);
                } else {
                    g1[2 * j]     = fma2(a1, w.x, g1[2 * j]);
                    g2[2 * j]     = fma2(a2, w.x, g2[2 * j]);
                    g1[2 * j + 1] = fma2(a1, w.y, g1[2 * j + 1]);
                    g2[2 * j + 1] = fma2(a2, w.y, g2[2 * j + 1]);
                }
            }
        }
#pragma unroll
        for (int q = 0; q < O_DIM; ++q) { u1[q] = g1[q]; u2[q] = g2[q]; }
    }

    // ---- final gated dot with dim sPerm[7], same rolling window ----
    float s0, s1, s2, s3;
    {
        const int d7 = sPerm[7];
        const ulonglong2* gp =
            (const ulonglong2*)(Bt + (size_t)d7 * O_DIM * NPAIR + i1);
        ulonglong2 tg[GWIN];
#pragma unroll
        for (int q = 0; q < GWIN; ++q) tg[q] = gp[(size_t)q * QSTRIDE];
        ull se1 = 0ULL, so1 = 0ULL, se2 = 0ULL, so2 = 0ULL;
#pragma unroll
        for (int q = 0; q < O_DIM; ++q) {
            ulonglong2 cur = tg[q % GWIN];
            if (q + GWIN < O_DIM)
                tg[q % GWIN] = gp[(size_t)(q + GWIN) * QSTRIDE];
            if (q & 1) {
                so1 = fma2(u1[q], cur.x, so1);
                so2 = fma2(u2[q], cur.y, so2);
            } else {
                se1 = fma2(u1[q], cur.x, se1);
                se2 = fma2(u2[q], cur.y, se2);
            }
        }
        unpack2(add2(se1, so1), s0, s1);
        unpack2(add2(se2, so2), s2, s3);
    }
    *(float4*)(g_scratch + (size_t)pc * NTOT + i1 * 2) = make_float4(s0, s1, s2, s3);
}

// 4 threads per output; each sums 35 pc slots (5 mean + 30 var; j%7==0 -> mean).
__global__ void reduce_kernel(float* __restrict__ out, int n) {
    int tid = threadIdx.x;
    int i = blockIdx.x * 64 + (tid >> 2);    // output sample
    int sub = tid & 3;
    if (i >= n) return;
    float m = 0.0f, v = 0.0f;
    int base = sub * 35;
#pragma unroll
    for (int j = 0; j < 35; ++j) {
        float s = g_scratch[(size_t)(base + j) * NTOT + i];
        if (j % 7 == 0) m += s; else v += s;
    }
    m += __shfl_xor_sync(0xFFFFFFFFu, m, 1);
    v += __shfl_xor_sync(0xFFFFFFFFu, v, 1);
    m += __shfl_xor_sync(0xFFFFFFFFu, m, 2);
    v += __shfl_xor_sync(0xFFFFFFFFu, v, 2);
    if (sub == 0) ((float2*)out)[i] = make_float2(m, v);
}

extern "C" void kernel_launch(void* const* d_in, const int* in_sizes, int n_in,
                              void* d_out, int out_size) {
    const float* X = (const float*)d_in[0];       // [N, 8]
    const int* perm = (const int*)d_in[1];        // [20, 8]
    const float* meanw0 = (const float*)d_in[2];  // [20, 1, 20]
    const float* meanw = (const float*)d_in[3];   // [7, 20, 20, 20]
    const float* varw0 = (const float*)d_in[4];   // [20, 1, 20]
    const float* varw = (const float*)d_in[5];    // [7, 20, 20, 20]
    float* out = (float*)d_out;                   // [N, 2]

    int N = in_sizes[0] / N_DIM;
    int ntiles = N / (4 * THREADS);               // 64 for N=32768

    prep_kernel<<<(394800 + 255) / 256, 256>>>(meanw0, meanw, varw0, varw);
    prep_basis_kernel<<<(NPAIR + 255) / 256, 256>>>(X);

    cudaFuncSetAttribute(main_kernel, cudaFuncAttributeMaxDynamicSharedMemorySize,
                         SMEM_BYTES);
    main_kernel<<<P_DIM * 7 * ntiles, THREADS, SMEM_BYTES>>>(perm, ntiles);

    reduce_kernel<<<(N + 63) / 64, 256>>>(out, N);
}